// round 11
// baseline (speedup 1.0000x reference)
#include <cuda_runtime.h>
#include <math.h>
#include <stdint.h>

// Problem constants
#define Bn   4
#define Nn   8192
#define Cc   384
#define Hh   12
#define Dd   2
#define Kk   256
#define Mm   32          // members per cluster
#define CHh  32          // channels per head
#define TOT  (Bn * Nn)   // 32768 rows
#define Zz   (Bn * Kk)   // 1024 clusters
#define TQ   128         // queries per attention CTA

typedef unsigned long long ull;

// ---------------------------------------------------------------------------
// packed f32x2 helpers. Reduction-packing: lanes hold (k, k+1) partial sums,
// combined by one horizontal add at the epilogue. No broadcast packs needed.
// ---------------------------------------------------------------------------
__device__ __forceinline__ void fma2(ull& d, ull a, ull b) {
    asm("fma.rn.f32x2 %0, %1, %2, %0;" : "+l"(d) : "l"(a), "l"(b));
}
__device__ __forceinline__ float hadd2(ull v) {
    unsigned int lo, hi;
    asm("mov.b64 {%0, %1}, %2;" : "=r"(lo), "=r"(hi) : "l"(v));
    return __uint_as_float(lo) + __uint_as_float(hi);
}

// ---------------------------------------------------------------------------
// Scratch (device globals: no allocation allowed in kernel_launch)
// ---------------------------------------------------------------------------
__device__ float g_posmax[Dd];
__device__ float g_meanfeat[Zz * Cc];
__device__ float g_kv[Zz * 2 * Cc];                  // [z][768]: key(384) | v(384)
__device__ float g_pmdot[Bn * Hh * Kk];
__device__ float g_Q[(size_t)TOT * Cc];              // scaled Q
__device__ float g_O[(size_t)TOT * Cc];              // attention output (pre-proj)

// ---------------------------------------------------------------------------
// K0: per-dimension max of pos (positive values -> int atomicMax is exact)
// ---------------------------------------------------------------------------
__global__ void posmax_init_kernel() {
    if (threadIdx.x < Dd) g_posmax[threadIdx.x] = 0.0f;
}

__global__ __launch_bounds__(256) void posmax_kernel(const float* __restrict__ pos) {
    __shared__ float s0[256];
    __shared__ float s1[256];
    int t = threadIdx.x;
    int gt = blockIdx.x * 256 + t;
    float m0 = 0.f, m1 = 0.f;
    const float2* p2 = (const float2*)pos;
    for (int i = gt; i < TOT; i += 256 * 64) {
        float2 v = p2[i];
        m0 = fmaxf(m0, v.x);
        m1 = fmaxf(m1, v.y);
    }
    s0[t] = m0; s1[t] = m1;
    __syncthreads();
    for (int st = 128; st > 0; st >>= 1) {
        if (t < st) {
            s0[t] = fmaxf(s0[t], s0[t + st]);
            s1[t] = fmaxf(s1[t], s1[t + st]);
        }
        __syncthreads();
    }
    if (t == 0) atomicMax((int*)&g_posmax[0], __float_as_int(s0[0]));
    if (t == 1) atomicMax((int*)&g_posmax[1], __float_as_int(s1[0]));
}

// ---------------------------------------------------------------------------
// K1: per-cluster mean of feat + pos mean + pm_dot
// ---------------------------------------------------------------------------
__global__ __launch_bounds__(128) void cluster_mean_kernel(
    const float* __restrict__ pos, const float* __restrict__ feat,
    const int* __restrict__ member_idx, const int* __restrict__ batch_idx,
    const float* __restrict__ pos_w, const float* __restrict__ pos_b)
{
    int z = blockIdx.x;
    int t = threadIdx.x;
    __shared__ int   idx[Mm];
    __shared__ int   bsh;
    __shared__ float pm[2];

    if (t < Mm) idx[t] = member_idx[z * Mm + t];
    if (t == 0) bsh = batch_idx[z * Mm];
    __syncthreads();
    int b = bsh;
    const float* fb = feat + (size_t)b * Nn * Cc;

    float a0 = 0.f, a1 = 0.f, a2 = 0.f;
    for (int m = 0; m < Mm; m++) {
        const float* fr = fb + (size_t)idx[m] * Cc;
        a0 += fr[t];
        a1 += fr[t + 128];
        a2 += fr[t + 256];
    }
    const float invM = 1.0f / (float)Mm;
    g_meanfeat[z * Cc + t]       = a0 * invM;
    g_meanfeat[z * Cc + t + 128] = a1 * invM;
    g_meanfeat[z * Cc + t + 256] = a2 * invM;

    if (t < Dd) {
        const float* pb = pos + (size_t)b * Nn * Dd;
        float s = 0.f;
        for (int m = 0; m < Mm; m++) s += pb[idx[m] * Dd + t];
        pm[t] = (s * invM) / g_posmax[t];
    }
    __syncthreads();
    if (t < Hh) {
        int kk = z & (Kk - 1);
        int bb = z >> 8;
        g_pmdot[(bb * Hh + t) * Kk + kk] =
            pm[0] * pos_w[t * Dd + 0] + pm[1] * pos_w[t * Dd + 1] + pos_b[t];
    }
}

// ---------------------------------------------------------------------------
// K2/K3/K5: reduction-packed f32x2 GEMM
//   C[M][Nc] = alpha*(A[M][384] @ W[Nc][384]^T + bias)
// 128x128 tile, BK=32, 512 threads, 8x4 microtile, k-pairs in FFMA2 lanes.
// Smem tiles are row-major (k contiguous) -> natural ulonglong2 operands.
// ---------------------------------------------------------------------------
__global__ __launch_bounds__(512, 1) void gemm128_kernel(
    const float* __restrict__ A, const float* __restrict__ W,
    const float* __restrict__ bias, float* __restrict__ C,
    int Nc, float alpha)
{
    __shared__ float As[128][36];
    __shared__ float Ws[128][36];
    const int t  = threadIdx.x;
    const int m0 = blockIdx.y * 128;
    const int n0 = blockIdx.x * 128;
    const int tm = t & 15;           // rows tm + 16*i, i<8
    const int tn = (t >> 4) * 4;     // cols tn..tn+3

    const int lrow = t >> 3;         // 0..63  (with +64 for second half)
    const int lc0  = (t & 7) * 4;    // 0..28

    ull acc[8][4] = {};

    // load tile 0
    #pragma unroll
    for (int i = 0; i < 2; i++) {
        int row = lrow + i * 64;
        *(float4*)&As[row][lc0] = *(const float4*)(A + (size_t)(m0 + row) * 384 + lc0);
        *(float4*)&Ws[row][lc0] = *(const float4*)(W + (size_t)(n0 + row) * 384 + lc0);
    }
    __syncthreads();

    for (int kt = 0; kt < 384; kt += 32) {
        float4 pa[2], pw[2];
        const bool pre = (kt + 32) < 384;
        if (pre) {
            #pragma unroll
            for (int i = 0; i < 2; i++) {
                int row = lrow + i * 64;
                pa[i] = *(const float4*)(A + (size_t)(m0 + row) * 384 + kt + 32 + lc0);
                pw[i] = *(const float4*)(W + (size_t)(n0 + row) * 384 + kt + 32 + lc0);
            }
        }
        #pragma unroll
        for (int c = 0; c < 32; c += 4) {
            ulonglong2 a[8];
            #pragma unroll
            for (int i = 0; i < 8; i++)
                a[i] = *(const ulonglong2*)&As[tm + 16 * i][c];
            ulonglong2 w[4];
            #pragma unroll
            for (int j = 0; j < 4; j++)
                w[j] = *(const ulonglong2*)&Ws[tn + j][c];
            #pragma unroll
            for (int i = 0; i < 8; i++)
                #pragma unroll
                for (int j = 0; j < 4; j++) {
                    fma2(acc[i][j], a[i].x, w[j].x);
                    fma2(acc[i][j], a[i].y, w[j].y);
                }
        }
        __syncthreads();
        if (pre) {
            #pragma unroll
            for (int i = 0; i < 2; i++) {
                int row = lrow + i * 64;
                *(float4*)&As[row][lc0] = pa[i];
                *(float4*)&Ws[row][lc0] = pw[i];
            }
            __syncthreads();
        }
    }

    float b0 = bias[n0 + tn + 0], b1 = bias[n0 + tn + 1];
    float b2 = bias[n0 + tn + 2], b3 = bias[n0 + tn + 3];
    #pragma unroll
    for (int i = 0; i < 8; i++) {
        int r = m0 + tm + 16 * i;
        float4 o;
        o.x = alpha * (hadd2(acc[i][0]) + b0);
        o.y = alpha * (hadd2(acc[i][1]) + b1);
        o.z = alpha * (hadd2(acc[i][2]) + b2);
        o.w = alpha * (hadd2(acc[i][3]) + b3);
        *(float4*)(C + (size_t)r * Nc + n0 + tn) = o;
    }
}

// ---------------------------------------------------------------------------
// K4: fused attention per (b, h, 128-query tile). 512 threads, 1 CTA/SM.
//   Phase 1: S[r][k] = Q.K^T + pm   (c-packed, 8x4 microtile, 2 k-passes)
//   Phase 2: vectorized softmax over k (4 segs/row)
//   Phase 3: O = P.V                 (k-packed, 4x2 microtile vs Vt[c][k])
// ---------------------------------------------------------------------------
#define SM_Q    0                       // [128][36]
#define SM_K    (128 * 36)              // [256][36]
#define SM_V    (SM_K + 256 * 36)       // [32][260]  Vt[c][k]
#define SM_S    (SM_V + 32 * 260)       // [128][260] S[r][k]
#define SM_PM   (SM_S + 128 * 260)      // [256]
#define SM_RM   (SM_PM + 256)           // [4][128]
#define SM_RS   (SM_RM + 512)           // [4][128]
#define SM_INV  (SM_RS + 512)           // [128]
#define ATTN_SMEM_FLOATS (SM_INV + 128)
#define ATTN_SMEM_BYTES  (ATTN_SMEM_FLOATS * 4)

__global__ __launch_bounds__(512, 1) void attn_kernel() {
    extern __shared__ float sm[];
    float* Qs   = sm + SM_Q;
    float* Ks   = sm + SM_K;
    float* Vt   = sm + SM_V;
    float* S    = sm + SM_S;
    float* pm   = sm + SM_PM;
    float* redM = sm + SM_RM;
    float* redS = sm + SM_RS;
    float* invS = sm + SM_INV;

    const int t  = threadIdx.x;
    const int b  = blockIdx.z;
    const int h  = blockIdx.y;
    const int n0 = blockIdx.x * TQ;

    // ---- loads: Q row-major, K row-major, V transposed ----
    {
        int r  = t >> 2;               // 0..127
        int c0 = (t & 3) * 8;          // 0,8,16,24
        const float* qrow = g_Q + ((size_t)b * Nn + n0 + r) * Cc + h * CHh + c0;
        *(float4*)&Qs[r * 36 + c0]     = *(const float4*)qrow;
        *(float4*)&Qs[r * 36 + c0 + 4] = *(const float4*)(qrow + 4);
    }
    const float* kvb = g_kv + (size_t)b * Kk * (2 * Cc);
    #pragma unroll
    for (int i = 0; i < 4; i++) {
        int f  = t + i * 512;          // 0..2047
        int k  = f >> 3;
        int c0 = (f & 7) * 4;
        *(float4*)&Ks[k * 36 + c0] =
            *(const float4*)&kvb[(size_t)k * (2 * Cc) + h * CHh + c0];
        float4 vv = *(const float4*)&kvb[(size_t)k * (2 * Cc) + Cc + h * CHh + c0];
        Vt[(c0 + 0) * 260 + k] = vv.x;
        Vt[(c0 + 1) * 260 + k] = vv.y;
        Vt[(c0 + 2) * 260 + k] = vv.z;
        Vt[(c0 + 3) * 260 + k] = vv.w;
    }
    if (t < 256) pm[t] = g_pmdot[((size_t)b * Hh + h) * Kk + t];
    __syncthreads();

    // ---- Phase 1: S = Q.K^T + pm (reduction-packed over c) ----
    {
        const int tm  = t & 15;            // rows tm + 16*i
        const int tk4 = (t >> 4) * 4;      // k cols (two passes: +0, +128)
        #pragma unroll
        for (int pass = 0; pass < 2; pass++) {
            const int kb = pass * 128 + tk4;
            ull acc[8][4] = {};
            #pragma unroll
            for (int c = 0; c < 32; c += 4) {
                ulonglong2 q[8];
                #pragma unroll
                for (int i = 0; i < 8; i++)
                    q[i] = *(const ulonglong2*)&Qs[(tm + 16 * i) * 36 + c];
                ulonglong2 kv[4];
                #pragma unroll
                for (int j = 0; j < 4; j++)
                    kv[j] = *(const ulonglong2*)&Ks[(kb + j) * 36 + c];
                #pragma unroll
                for (int i = 0; i < 8; i++)
                    #pragma unroll
                    for (int j = 0; j < 4; j++) {
                        fma2(acc[i][j], q[i].x, kv[j].x);
                        fma2(acc[i][j], q[i].y, kv[j].y);
                    }
            }
            float p0 = pm[kb + 0], p1 = pm[kb + 1], p2 = pm[kb + 2], p3 = pm[kb + 3];
            #pragma unroll
            for (int i = 0; i < 8; i++) {
                int r = tm + 16 * i;
                float4 o;
                o.x = hadd2(acc[i][0]) + p0;
                o.y = hadd2(acc[i][1]) + p1;
                o.z = hadd2(acc[i][2]) + p2;
                o.w = hadd2(acc[i][3]) + p3;
                *(float4*)&S[r * 260 + kb] = o;
            }
        }
    }
    __syncthreads();

    // ---- Phase 2: softmax per row (4 segs of 64 k per row, vectorized) ----
    {
        const int r   = t & 127;
        const int seg = t >> 7;            // 0..3
        const int kb  = seg * 64;
        float* Srow = &S[r * 260 + kb];
        float mx = -1e30f;
        #pragma unroll
        for (int kk = 0; kk < 64; kk += 4) {
            float4 v = *(const float4*)&Srow[kk];
            mx = fmaxf(mx, fmaxf(fmaxf(v.x, v.y), fmaxf(v.z, v.w)));
        }
        redM[seg * 128 + r] = mx;
        __syncthreads();
        float m = fmaxf(fmaxf(redM[r], redM[128 + r]),
                        fmaxf(redM[256 + r], redM[384 + r]));
        float s = 0.f;
        #pragma unroll
        for (int kk = 0; kk < 64; kk += 4) {
            float4 v = *(const float4*)&Srow[kk];
            v.x = __expf(v.x - m);
            v.y = __expf(v.y - m);
            v.z = __expf(v.z - m);
            v.w = __expf(v.w - m);
            *(float4*)&Srow[kk] = v;
            s += (v.x + v.y) + (v.z + v.w);
        }
        redS[seg * 128 + r] = s;
        __syncthreads();
        if (seg == 0)
            invS[r] = 1.0f / (redS[r] + redS[128 + r] + redS[256 + r] + redS[384 + r]);
    }
    __syncthreads();

    // ---- Phase 3: O = P.V (reduction-packed over k) ----
    {
        const int c2 = (t & 15) * 2;       // 2 channels
        const int r4 = (t >> 4) * 4;       // 4 query rows
        ull acc[4][2] = {};
        #pragma unroll 4
        for (int k0 = 0; k0 < 256; k0 += 4) {
            ulonglong2 p[4];
            #pragma unroll
            for (int i = 0; i < 4; i++)
                p[i] = *(const ulonglong2*)&S[(r4 + i) * 260 + k0];
            ulonglong2 v[2];
            #pragma unroll
            for (int j = 0; j < 2; j++)
                v[j] = *(const ulonglong2*)&Vt[(c2 + j) * 260 + k0];
            #pragma unroll
            for (int i = 0; i < 4; i++)
                #pragma unroll
                for (int j = 0; j < 2; j++) {
                    fma2(acc[i][j], p[i].x, v[j].x);
                    fma2(acc[i][j], p[i].y, v[j].y);
                }
        }
        #pragma unroll
        for (int i = 0; i < 4; i++) {
            float inv = invS[r4 + i];
            float2 o;
            o.x = hadd2(acc[i][0]) * inv;
            o.y = hadd2(acc[i][1]) * inv;
            *(float2*)(g_O + ((size_t)b * Nn + n0 + r4 + i) * Cc + h * CHh + c2) = o;
        }
    }
}

// ---------------------------------------------------------------------------
// Launch
// ---------------------------------------------------------------------------
extern "C" void kernel_launch(void* const* d_in, const int* in_sizes, int n_in,
                              void* d_out, int out_size)
{
    const float* pos        = (const float*)d_in[0];
    const float* feat       = (const float*)d_in[1];
    const int*   member_idx = (const int*)  d_in[2];
    const int*   batch_idx  = (const int*)  d_in[3];
    const float* qkv_w      = (const float*)d_in[4];
    const float* qkv_b      = (const float*)d_in[5];
    const float* pos_w      = (const float*)d_in[6];
    const float* pos_b      = (const float*)d_in[7];
    const float* proj_w     = (const float*)d_in[8];
    const float* proj_b     = (const float*)d_in[9];
    (void)in_sizes; (void)n_in; (void)out_size;

    float *p_meanfeat, *p_kv, *p_Q, *p_O;
    cudaGetSymbolAddress((void**)&p_meanfeat, g_meanfeat);
    cudaGetSymbolAddress((void**)&p_kv,       g_kv);
    cudaGetSymbolAddress((void**)&p_Q,        g_Q);
    cudaGetSymbolAddress((void**)&p_O,        g_O);

    cudaFuncSetAttribute(attn_kernel,
                         cudaFuncAttributeMaxDynamicSharedMemorySize,
                         ATTN_SMEM_BYTES);

    // K0: pos max
    posmax_init_kernel<<<1, 32>>>();
    posmax_kernel<<<64, 256>>>(pos);

    // K1: cluster means + pm_dot
    cluster_mean_kernel<<<Zz, 128>>>(pos, feat, member_idx, batch_idx, pos_w, pos_b);

    // K2: kv_mean = mean_feat @ W_kv^T + b_kv  (rows 384..1151 of qkv_w)
    {
        dim3 grid((2 * Cc) / 128, Zz / 128);
        gemm128_kernel<<<grid, 512>>>(p_meanfeat, qkv_w + Cc * Cc, qkv_b + Cc,
                                      p_kv, 2 * Cc, 1.0f);
    }

    // K3: Qs = scale * (feat @ W_q^T + b_q)
    {
        dim3 grid(Cc / 128, TOT / 128);
        const float scale = 0.17677669529663687f;   // 32^{-1/2}
        gemm128_kernel<<<grid, 512>>>(feat, qkv_w, qkv_b, p_Q, Cc, scale);
    }

    // K4: fused attention
    attn_kernel<<<dim3(Nn / TQ, Hh, Bn), 512, ATTN_SMEM_BYTES>>>();

    // K5: out = O @ proj_w^T + proj_b
    {
        dim3 grid(Cc / 128, TOT / 128);
        gemm128_kernel<<<grid, 512>>>(p_O, proj_w, proj_b, (float*)d_out,
                                      Cc, 1.0f);
    }
}